// round 17
// baseline (speedup 1.0000x reference)
#include <cuda_runtime.h>
#include <cuda_fp16.h>
#include <cuda_pipeline.h>
#include <math.h>
#include <stdint.h>

#define BSZ 64
#define SEQ 256
#define MROWS (BSZ*SEQ)   // 16384
#define INF 1024
#define UFD 512
#define OFD 512

#define STAGE64 (2*128*144)                   // 36864: one 2-tile stage @BK=64
#define STASH_B (32*256*4)                    // 32768: d-acc stash (half2)
#define SMEM_DU   (2*STAGE64 + STASH_B)       // 106496 (2-stage + stash)
#define SMEM_G3   (3*STAGE64)                 // 110592 (3-stage)
#define SMEM_ATT  (SMEM_G3 + 1024 + 16)       // + srow/scol + flag

// ---------------- scratch (__device__ globals; no runtime alloc) ----------------
__device__ __align__(16) __half g_Xdh[MROWS*INF];
__device__ __align__(16) __half g_Xuh[MROWS*UFD];
__device__ __align__(16) __half g_Wdh[OFD*INF];
__device__ __align__(16) __half g_Wuh[OFD*UFD];
__device__ __align__(16) __half g_Wth[OFD*OFD];   // W^T: Wt[e][d] = W[d][e]
__device__ __align__(16) __half g_Dh[MROWS*OFD];  // gated d
__device__ __align__(16) __half g_Uh[MROWS*OFD];  // gated u
__device__ __align__(16) __half g_Eh[MROWS*OFD];
__device__ float g_rowpart[BSZ*SEQ*2];
__device__ float g_colpart[BSZ*SEQ*2];
__device__ int   g_cnt[BSZ];                      // per-batch completion counters

// ---------------- helpers ----------------
__device__ __forceinline__ uint32_t smem_to_u32(const void* p) {
    uint32_t a;
    asm("{ .reg .u64 t; cvta.to.shared.u64 t, %1; cvt.u32.u64 %0, t; }" : "=r"(a) : "l"(p));
    return a;
}
__device__ __forceinline__ void ldmx4(uint32_t r[4], uint32_t addr) {
    asm volatile("ldmatrix.sync.aligned.m8n8.x4.shared.b16 {%0,%1,%2,%3}, [%4];"
        : "=r"(r[0]), "=r"(r[1]), "=r"(r[2]), "=r"(r[3]) : "r"(addr));
}
__device__ __forceinline__ void mma16816(float c[4], const uint32_t a[4], const uint32_t b[2]) {
    asm volatile("mma.sync.aligned.m16n8k16.row.col.f32.f16.f16.f32 "
        "{%0,%1,%2,%3}, {%4,%5,%6,%7}, {%8,%9}, {%0,%1,%2,%3};"
        : "+f"(c[0]), "+f"(c[1]), "+f"(c[2]), "+f"(c[3])
        : "r"(a[0]), "r"(a[1]), "r"(a[2]), "r"(a[3]), "r"(b[0]), "r"(b[1]));
}
__device__ __forceinline__ float sigm(float x) { return 1.0f / (1.0f + __expf(-x)); }
__device__ __forceinline__ float fast_tanh(float x) {
    float y; asm("tanh.approx.f32 %0, %1;" : "=f"(y) : "f"(x)); return y;
}
__device__ __forceinline__ uint32_t packh(float v0, float v1) {
    __half2 h; h.x = __float2half_rn(v0); h.y = __float2half_rn(v1);
    return *reinterpret_cast<uint32_t*>(&h);
}

// ---------------- shared compute body for one BK=64 k-tile ----------------
__device__ __forceinline__ void tile_compute64(
    uint32_t stg, int ROWB, int TILEB,
    uint32_t a_row, uint32_t a_ko, uint32_t b_row, uint32_t b_ko,
    int wm, int wn, float (&acc)[4][4][4])
{
    uint32_t aoff = stg + (wm + a_row) * ROWB + a_ko;
    uint32_t boff = stg + TILEB + (wn + b_row) * ROWB + b_ko;
    #pragma unroll
    for (int kk = 0; kk < 4; kk++) {
        uint32_t kb = (uint32_t)(kk * 32);
        uint32_t bh[2][4];
        #pragma unroll
        for (int nf2 = 0; nf2 < 2; nf2++)
            ldmx4(bh[nf2], boff + nf2 * (16 * ROWB) + kb);
        #pragma unroll
        for (int mf = 0; mf < 4; mf++) {
            uint32_t ah[4];
            ldmx4(ah, aoff + mf * (16 * ROWB) + kb);
            #pragma unroll
            for (int nf = 0; nf < 4; nf++)
                mma16816(acc[mf][nf], ah, &bh[nf >> 1][(nf & 1) * 2]);
        }
    }
}

// ---------------- 2-stage mainloop (runtime K), BK=64 — for k_du ----------------
__device__ __forceinline__ void gemm1(
    const __half* __restrict__ Ah, int lda,
    const __half* __restrict__ Bh, int ldb,
    int K, char* smem, float (&acc)[4][4][4])
{
    constexpr int ROWB = 144, TILEB = 128 * 144, STAGEB = 2 * TILEB;
    int tid = threadIdx.x;
    int lane = tid & 31, wid = tid >> 5;
    int wm = (wid & 1) * 64, wn = (wid >> 1) * 32;
    uint32_t sb = smem_to_u32(smem);

    auto fill = [&](int s, int k0) {
        #pragma unroll
        for (int t = 0; t < 2; t++) {
            const __half* bp = (t == 0) ? Ah : Bh;
            int ld = (t == 0) ? lda : ldb;
            #pragma unroll
            for (int h = 0; h < 4; h++) {
                int chunk = h * 256 + tid;              // 128 rows x 8 chunks
                int row = chunk >> 3, c4 = chunk & 7;
                __pipeline_memcpy_async(
                    smem + s * STAGEB + t * TILEB + row * ROWB + c4 * 16,
                    bp + (size_t)row * ld + k0 + c4 * 8, 16);
            }
        }
        __pipeline_commit();
    };

    uint32_t a_row = (uint32_t)(lane & 15);
    uint32_t a_ko  = (uint32_t)((lane >> 4) << 4);
    uint32_t b_row = (uint32_t)((lane & 7) + ((lane >> 4) << 3));
    uint32_t b_ko  = (uint32_t)(((lane >> 3) & 1) << 4);

    int nk = K >> 6;
    fill(0, 0);
    for (int kt = 0; kt < nk; kt++) {
        __pipeline_wait_prior(0);
        __syncthreads();
        if (kt + 1 < nk) fill((kt + 1) & 1, (kt + 1) * 64);
        tile_compute64(sb + (uint32_t)((kt & 1) * STAGEB), ROWB, TILEB,
                       a_row, a_ko, b_row, b_ko, wm, wn, acc);
    }
    // No trailing sync: next gemm's first in-loop sync covers buffer reuse
    // (nk even -> last-consumed buffer is 1, next fill targets buffer 0).
}

// ---------------- 3-stage fully-unrolled mainloop (K constexpr), BK=64 --------
template<int K>
__device__ __forceinline__ void gemm3(
    const __half* __restrict__ Ah, int lda,
    const __half* __restrict__ Bh, int ldb,
    char* smem, float (&acc)[4][4][4])
{
    constexpr int ROWB = 144, TILEB = 128 * 144, STAGEB = 2 * TILEB;
    constexpr int nk = K / 64;
    int tid = threadIdx.x;
    int lane = tid & 31, wid = tid >> 5;
    int wm = (wid & 1) * 64, wn = (wid >> 1) * 32;
    uint32_t sb = smem_to_u32(smem);

    auto fill = [&](int s, int k0) {
        #pragma unroll
        for (int t = 0; t < 2; t++) {
            const __half* bp = (t == 0) ? Ah : Bh;
            int ld = (t == 0) ? lda : ldb;
            #pragma unroll
            for (int h = 0; h < 4; h++) {
                int chunk = h * 256 + tid;
                int row = chunk >> 3, c4 = chunk & 7;
                __pipeline_memcpy_async(
                    smem + s * STAGEB + t * TILEB + row * ROWB + c4 * 16,
                    bp + (size_t)row * ld + k0 + c4 * 8, 16);
            }
        }
        __pipeline_commit();
    };

    uint32_t a_row = (uint32_t)(lane & 15);
    uint32_t a_ko  = (uint32_t)((lane >> 4) << 4);
    uint32_t b_row = (uint32_t)((lane & 7) + ((lane >> 4) << 3));
    uint32_t b_ko  = (uint32_t)(((lane >> 3) & 1) << 4);

    fill(0, 0);
    fill(1, 64);
    #pragma unroll
    for (int kt = 0; kt < nk; kt++) {
        if (kt + 1 < nk) __pipeline_wait_prior(1);
        else             __pipeline_wait_prior(0);
        __syncthreads();              // all warps done with buffer (kt+2)%3
        if (kt + 2 < nk) fill((kt + 2) % 3, (kt + 2) * 64);
        tile_compute64(sb + (uint32_t)((kt % 3) * STAGEB), ROWB, TILEB,
                       a_row, a_ko, b_row, b_ko, wm, wn, acc);
    }
}

// ===========================================================================
// Single conversion kernel: Xd, Xu, Wd, Wu (straight) + W transpose.
// Block 0 also resets the per-batch completion counters for this replay.
// ===========================================================================
#define NBLK_XD (MROWS*INF/1024)   // 16384
#define NBLK_XU (MROWS*UFD/1024)   // 8192
#define NBLK_WD (OFD*INF/1024)     // 512
#define NBLK_WU (OFD*UFD/1024)     // 256
#define NBLK_WT (OFD*OFD/256)      // 1024
#define NBLK_CVT (NBLK_XD + NBLK_XU + NBLK_WD + NBLK_WU + NBLK_WT)

__global__ __launch_bounds__(256) void k_cvt(
    const float* __restrict__ Xd, const float* __restrict__ Xu,
    const float* __restrict__ Wd, const float* __restrict__ Wu,
    const float* __restrict__ W)
{
    int blk = blockIdx.x;
    if (blk == 0 && threadIdx.x < BSZ) g_cnt[threadIdx.x] = 0;
    if (blk < NBLK_XD + NBLK_XU + NBLK_WD + NBLK_WU) {
        const float* src; __half* dst; int i;
        if (blk < NBLK_XD) { src = Xd; dst = g_Xdh; i = blk; }
        else if (blk < NBLK_XD + NBLK_XU) { src = Xu; dst = g_Xuh; i = blk - NBLK_XD; }
        else if (blk < NBLK_XD + NBLK_XU + NBLK_WD) { src = Wd; dst = g_Wdh; i = blk - NBLK_XD - NBLK_XU; }
        else { src = Wu; dst = g_Wuh; i = blk - NBLK_XD - NBLK_XU - NBLK_WD; }
        int idx = (i * 256 + threadIdx.x) * 4;
        float4 v = *(const float4*)(src + idx);
        *(uint2*)(dst + idx) = make_uint2(packh(v.x, v.y), packh(v.z, v.w));
    } else {
        int idx = (blk - (NBLK_CVT - NBLK_WT)) * 256 + threadIdx.x;  // = e*512 + d
        int e = idx >> 9, d = idx & 511;
        g_Wth[idx] = __float2half_rn(W[d * 512 + e]);
    }
}

// ===========================================================================
// Fused d/u GEMMs + gating.  grid (4, 128), block 256, BK=64, 2-stage
// ===========================================================================
__global__ __launch_bounds__(256, 2) void k_du(const float* __restrict__ bd,
                                               const float* __restrict__ bu)
{
    extern __shared__ __align__(16) char smem[];
    __half2* stash = (__half2*)(smem + 2 * STAGE64);   // 32 x 256 half2, [j][tid]
    int tid = threadIdx.x;
    int row0 = blockIdx.y * 128, col0 = blockIdx.x * 128;

    float acc[4][4][4] = {};
    gemm1(g_Xdh + (size_t)row0 * INF, INF,
          g_Wdh + (size_t)col0 * INF, INF, INF, smem, acc);

    // stash d-acc as half2 (private slots, conflict-free [j][tid]; no sync)
    {
        float* af = &acc[0][0][0];
        #pragma unroll
        for (int j = 0; j < 32; j++) {
            stash[j * 256 + tid] = __floats2half2_rn(af[2 * j], af[2 * j + 1]);
            af[2 * j] = 0.0f; af[2 * j + 1] = 0.0f;
        }
    }

    gemm1(g_Xuh + (size_t)row0 * UFD, UFD,
          g_Wuh + (size_t)col0 * UFD, UFD, UFD, smem, acc);

    int lane = tid & 31, wid = tid >> 5;
    int wm = (wid & 1) * 64, wn = (wid >> 1) * 32;
    int rb = row0 + wm + (lane >> 2);
    int cb = col0 + wn + 2 * (lane & 3);
    #pragma unroll
    for (int nf = 0; nf < 4; nf++) {
        int c = cb + nf * 8;
        float bd0 = bd[c], bd1 = bd[c + 1];
        float bu0 = bu[c], bu1 = bu[c + 1];
        #pragma unroll
        for (int mf = 0; mf < 4; mf++)
            #pragma unroll
            for (int rr = 0; rr < 2; rr++) {
                int r = rb + mf * 16 + rr * 8;
                size_t idx = (size_t)r * OFD + c;
                int si = (mf * 4 + nf) * 4 + rr * 2;       // even
                float2 dp = __half22float2(stash[(si >> 1) * 256 + tid]);
                float d00 = dp.x + bd0;
                float d01 = dp.y + bd1;
                float u00 = acc[mf][nf][rr * 2]     + bu0;
                float u01 = acc[mf][nf][rr * 2 + 1] + bu1;
                float d10 = d00 * sigm(u00);
                float d11 = d01 * sigm(u01);
                float u10 = u00 * sigm(d10);
                float u11 = u01 * sigm(d11);
                *(uint32_t*)(g_Dh + idx) = packh(d10, d11);
                *(uint32_t*)(g_Uh + idx) = packh(u10, u11);
            }
    }
}

// ===========================================================================
// E = D @ W (via W^T), write fp16.  grid (4, 128), block 256, 3-stage
// ===========================================================================
__global__ __launch_bounds__(256, 2) void k_e(void)
{
    extern __shared__ __align__(16) char smem[];
    int row0 = blockIdx.y * 128, col0 = blockIdx.x * 128;
    float acc[4][4][4] = {};
    gemm3<OFD>(g_Dh + (size_t)row0 * OFD, OFD,
               g_Wth + (size_t)col0 * OFD, OFD, smem, acc);

    int tid = threadIdx.x, lane = tid & 31, wid = tid >> 5;
    int wm = (wid & 1) * 64, wn = (wid >> 1) * 32;
    int rb = row0 + wm + (lane >> 2);
    int cb = col0 + wn + 2 * (lane & 3);
    #pragma unroll
    for (int mf = 0; mf < 4; mf++)
        #pragma unroll
        for (int nf = 0; nf < 4; nf++)
            #pragma unroll
            for (int rr = 0; rr < 2; rr++) {
                int r = rb + mf * 16 + rr * 8;
                int c = cb + nf * 8;
                *(uint32_t*)(g_Eh + (size_t)r * OFD + c) =
                    packh(acc[mf][nf][rr * 2], acc[mf][nf][rr * 2 + 1]);
            }
}

// ===========================================================================
// att tile = tanh(E_b @ U_b^T); row/col partial sums; the LAST of the 4 CTAs
// of each batch runs the softmax + weighted-sum epilogue (threadfence-
// reduction pattern).  grid (2 rt, 2 st, 64 b), 3-stage.
// ===========================================================================
__global__ __launch_bounds__(256, 2) void k_att(float* __restrict__ out)
{
    extern __shared__ __align__(16) char smem[];
    float* srow = (float*)(smem + SMEM_G3);
    float* scol = srow + 128;
    int* flag = (int*)(scol + 128);
    int b = blockIdx.z, st = blockIdx.y, rt = blockIdx.x;
    int tid = threadIdx.x;
    if (tid < 128) { srow[tid] = 0.0f; scol[tid] = 0.0f; }
    // ordered before atomics below by the mainloop's __syncthreads

    float acc[4][4][4] = {};
    size_t ar = (size_t)(b * SEQ + st * 128) * OFD;
    size_t br = (size_t)(b * SEQ + rt * 128) * OFD;
    gemm3<OFD>(g_Eh + ar, OFD, g_Uh + br, OFD, smem, acc);

    int lane = tid & 31, wid = tid >> 5;
    int wm = (wid & 1) * 64, wn = (wid >> 1) * 32;
    int rb = wm + (lane >> 2);
    int cb = wn + 2 * (lane & 3);

    float t[4][4][4];
    #pragma unroll
    for (int mf = 0; mf < 4; mf++)
        #pragma unroll
        for (int nf = 0; nf < 4; nf++)
            #pragma unroll
            for (int e = 0; e < 4; e++)
                t[mf][nf][e] = fast_tanh(acc[mf][nf][e]);

    #pragma unroll
    for (int mf = 0; mf < 4; mf++) {
        float s0 = 0.0f, s1 = 0.0f;
        #pragma unroll
        for (int nf = 0; nf < 4; nf++) {
            s0 += t[mf][nf][0] + t[mf][nf][1];
            s1 += t[mf][nf][2] + t[mf][nf][3];
        }
        atomicAdd(&srow[rb + mf * 16], s0);
        atomicAdd(&srow[rb + mf * 16 + 8], s1);
    }
    #pragma unroll
    for (int nf = 0; nf < 4; nf++) {
        float c0 = 0.0f, c1 = 0.0f;
        #pragma unroll
        for (int mf = 0; mf < 4; mf++) {
            c0 += t[mf][nf][0] + t[mf][nf][2];
            c1 += t[mf][nf][1] + t[mf][nf][3];
        }
        atomicAdd(&scol[cb + nf * 8], c0);
        atomicAdd(&scol[cb + nf * 8 + 1], c1);
    }
    __syncthreads();

    if (tid < 128) {
        g_rowpart[(size_t)(b * SEQ + st * 128 + tid) * 2 + rt] = srow[tid];
        g_colpart[(size_t)(b * SEQ + rt * 128 + tid) * 2 + st] = scol[tid];
    }
    __threadfence();
    __syncthreads();
    if (tid == 0) *flag = atomicAdd(&g_cnt[b], 1);
    __syncthreads();
    if (*flag != 3) return;          // not the last CTA of this batch
    __threadfence();

    // ---- epilogue for batch b (stage buffers are dead; reuse as smem) ----
    float* sd  = (float*)smem;       // 256
    float* su  = sd + 256;           // 256
    float* red = su + 256;           // 256

    {
        const float* rp = &g_rowpart[(size_t)(b * SEQ + tid) * 2];
        sd[tid] = (rp[0] + rp[1]) * (1.0f / 256.0f);
        const float* cp = &g_colpart[(size_t)(b * SEQ + tid) * 2];
        su[tid] = (cp[0] + cp[1]) * (1.0f / 256.0f);
    }
    __syncthreads();

    // softmax sd
    {
        red[tid] = sd[tid]; __syncthreads();
        for (int off = 128; off > 0; off >>= 1) {
            if (tid < off) red[tid] = fmaxf(red[tid], red[tid + off]);
            __syncthreads();
        }
        float mx = red[0]; __syncthreads();
        float e = expf(sd[tid] - mx);
        red[tid] = e; __syncthreads();
        for (int off = 128; off > 0; off >>= 1) {
            if (tid < off) red[tid] += red[tid + off];
            __syncthreads();
        }
        float inv = 1.0f / red[0]; __syncthreads();
        sd[tid] = e * inv;
    }
    __syncthreads();
    // softmax su
    {
        red[tid] = su[tid]; __syncthreads();
        for (int off = 128; off > 0; off >>= 1) {
            if (tid < off) red[tid] = fmaxf(red[tid], red[tid + off]);
            __syncthreads();
        }
        float mx = red[0]; __syncthreads();
        float e = expf(su[tid] - mx);
        red[tid] = e; __syncthreads();
        for (int off = 128; off > 0; off >>= 1) {
            if (tid < off) red[tid] += red[tid + off];
            __syncthreads();
        }
        float inv = 1.0f / red[0]; __syncthreads();
        su[tid] = e * inv;
    }
    __syncthreads();

    // weighted sums: thread t handles cols t and t+256
    int c0 = tid, c1 = tid + 256;
    const __half* Dp = g_Dh + (size_t)(b * SEQ) * OFD;
    const __half* Up = g_Uh + (size_t)(b * SEQ) * OFD;
    float ad0 = 0.0f, ad1 = 0.0f, au0 = 0.0f, au1 = 0.0f;
    #pragma unroll 4
    for (int s = 0; s < SEQ; s++) {
        float w = sd[s], v = su[s];
        size_t rowb = (size_t)s * OFD;
        ad0 += w * __half2float(Dp[rowb + c0]);
        ad1 += w * __half2float(Dp[rowb + c1]);
        au0 += v * __half2float(Up[rowb + c0]);
        au1 += v * __half2float(Up[rowb + c1]);
    }
    out[(size_t)b * OFD + c0] = ad0;
    out[(size_t)b * OFD + c1] = ad1;
    out[(size_t)BSZ * OFD + (size_t)b * OFD + c0] = au0;
    out[(size_t)BSZ * OFD + (size_t)b * OFD + c1] = au1;
}

// ===========================================================================
extern "C" void kernel_launch(void* const* d_in, const int* in_sizes, int n_in,
                              void* d_out, int out_size)
{
    (void)in_sizes; (void)n_in; (void)out_size;
    const float* Xd = (const float*)d_in[0];
    const float* Xu = (const float*)d_in[1];
    const float* Wd = (const float*)d_in[2];
    const float* bd = (const float*)d_in[3];
    const float* Wu = (const float*)d_in[4];
    const float* bu = (const float*)d_in[5];
    const float* W  = (const float*)d_in[6];
    float* out = (float*)d_out;

    cudaFuncSetAttribute(k_du,  cudaFuncAttributeMaxDynamicSharedMemorySize, SMEM_DU);
    cudaFuncSetAttribute(k_e,   cudaFuncAttributeMaxDynamicSharedMemorySize, SMEM_G3);
    cudaFuncSetAttribute(k_att, cudaFuncAttributeMaxDynamicSharedMemorySize, SMEM_ATT);

    k_cvt<<<NBLK_CVT, 256>>>(Xd, Xu, Wd, Wu, W);

    dim3 g1(OFD / 128, MROWS / 128);
    k_du<<<g1, 256, SMEM_DU>>>(bd, bu);
    k_e<<<g1, 256, SMEM_G3>>>();
    dim3 g3(2, 2, BSZ);
    k_att<<<g3, 256, SMEM_ATT>>>(out);
}